// round 10
// baseline (speedup 1.0000x reference)
#include <cuda_runtime.h>

#define ITEMS 32
#define BLOCK 256
#define WT    48                     // warmup threads
#define WARM  (WT * ITEMS)           // 1536 warmup samples: 0.99^1536 ~ 2e-7
#define OUTS  ((BLOCK - WT) * ITEMS) // 6656 output samples per block
#define NWARP (BLOCK / 32)

__device__ __forceinline__ void get_params(const float* __restrict__ p,
                                           float& c1, float& c2,
                                           float& attack, float& decay, float& gain) {
    attack = fmaxf(p[0], 1e-7f);
    decay  = fmaxf(p[1], 1e-7f);
    c1 = fminf(fmaxf(p[2], 1e-7f), 0.99f);   // lowpass
    c2 = fminf(fmaxf(p[3], 1e-7f), 0.99f);   // highpass
    gain = fmaxf(p[4], 1e-7f);
}

__device__ __forceinline__ void mat_mul(float& c00, float& c10, float& c11,
                                        float a00, float a10, float a11,
                                        float b00, float b10, float b11) {
    c00 = a00 * b00;
    c10 = fmaf(a10, b00, a11 * b10);
    c11 = a11 * b11;
}

__device__ __forceinline__ void mat_sq(float& m00, float& m10, float& m11) {
    float n00 = m00 * m00;
    float n10 = m10 * (m00 + m11);
    float n11 = m11 * m11;
    m00 = n00; m10 = n10; m11 = n11;
}

// ---------------------------------------------------------------------------
// Single pass: per-block warmup (zero-state, 1536 samples) + intra-block scan
// + seeded replay + envelope + store. No inter-block communication.
// ---------------------------------------------------------------------------
__global__ void __launch_bounds__(BLOCK, 5)
ng_one(const float* __restrict__ params, const float* __restrict__ x,
       float* __restrict__ out, int n) {
    float c1, c2, at, de, g;
    get_params(params, c1, c2, at, de, g);
    const float b1 = 1.0f - c1;
    const float dcoef = c2 * (c1 - 1.0f);
    const float bb = c2 * b1;

    const int tid  = threadIdx.x;
    const int lane = tid & 31, wid = tid >> 5;
    const long block_base = (long)blockIdx.x * OUTS - WARM;   // may be negative (bid 0)
    const long tbase = block_base + (long)tid * ITEMS;
    const bool inr = (tbase >= 0) && (tbase + ITEMS <= n);

    // ---- stride-4 zero-state sweep over this thread's 32 samples ----
    const float A2_00 = c1 * c1, A2_10 = dcoef * (c1 + c2), A2_11 = c2 * c2;
    const float A4_00 = A2_00 * A2_00, A4_10 = A2_10 * (A2_00 + A2_11), A4_11 = A2_11 * A2_11;
    const float q0x = b1,       q0y = bb;
    const float q1x = c1 * q0x, q1y = fmaf(dcoef, q0x, c2 * q0y);
    const float q2x = c1 * q1x, q2y = fmaf(dcoef, q1x, c2 * q1y);
    const float q3x = c1 * q2x, q3y = fmaf(dcoef, q2x, c2 * q2y);

    float v0 = 0.0f, v1 = 0.0f;
    if (inr) {
        const float4* xp = (const float4*)(x + tbase);
        #pragma unroll
        for (int k = 0; k < ITEMS / 4; k++) {
            float4 q = xp[k];
            float u0 = fmaf(q2x, q.y, q3x * q.x) + fmaf(q0x, q.w, q1x * q.z);
            float u1 = fmaf(q2y, q.y, q3y * q.x) + fmaf(q0y, q.w, q1y * q.z);
            float v0n = fmaf(A4_00, v0, u0);
            v1 = fmaf(A4_10, v0, fmaf(A4_11, v1, u1));
            v0 = v0n;
        }
    } else if (tbase + ITEMS > 0 && tbase < n) {
        // boundary thread (block 0 prefix or global tail): serial, masked
        #pragma unroll
        for (int j = 0; j < ITEMS; j++) {
            long idx = tbase + j;
            float xn = (idx >= 0 && idx < n) ? x[idx] : 0.0f;
            float t  = fmaf(dcoef, v0, bb * xn);
            v1 = fmaf(c2, v1, t);
            v0 = fmaf(c1, v0, b1 * xn);
        }
    } // else: fully out of range -> state stays zero

    // ---- P = A^32 (5 squarings) ----
    float pk00 = c1, pk10 = dcoef, pk11 = c2;
    #pragma unroll
    for (int k = 0; k < 5; k++) mat_sq(pk00, pk10, pk11);

    // ---- vector-only KS scan with constant round matrices; build Ml = P^lane ----
    float Ml00 = 1.0f, Ml10 = 0.0f, Ml11 = 1.0f;
    #pragma unroll
    for (int k = 0; k < 5; k++) {
        int dd = 1 << k;
        float o0 = __shfl_up_sync(0xffffffffu, v0, dd);
        float o1 = __shfl_up_sync(0xffffffffu, v1, dd);
        if (lane >= dd) {
            v0 = fmaf(pk00, o0, v0);
            v1 = fmaf(pk10, o0, fmaf(pk11, o1, v1));
        }
        if ((lane >> k) & 1) {
            float t00, t10, t11;
            mat_mul(t00, t10, t11, Ml00, Ml10, Ml11, pk00, pk10, pk11);
            Ml00 = t00; Ml10 = t10; Ml11 = t11;
        }
        mat_sq(pk00, pk10, pk11);   // after loop: pk = P^32 (warp-total matrix)
    }

    // warp-exclusive vector
    float ve0 = __shfl_up_sync(0xffffffffu, v0, 1);
    float ve1 = __shfl_up_sync(0xffffffffu, v1, 1);
    if (lane == 0) { ve0 = 0.0f; ve1 = 0.0f; }

    __shared__ float2 wtotv[NWARP];
    __shared__ float2 prevv[NWARP];
    if (lane == 31) wtotv[wid] = make_float2(v0, v1);
    __syncthreads();
    if (tid == 0) {
        float s0 = 0.0f, s1 = 0.0f;
        #pragma unroll
        for (int w = 0; w < NWARP; w++) {
            prevv[w] = make_float2(s0, s1);
            float2 wv = wtotv[w];
            float ns0 = fmaf(pk00, s0, wv.x);
            s1 = fmaf(pk10, s0, fmaf(pk11, s1, wv.y));
            s0 = ns0;
        }
    }
    __syncthreads();

    // ---- output threads only: seed, replay, envelope, store ----
    if (tid >= WT) {
        float2 pv = prevv[wid];
        float y1 = fmaf(Ml00, pv.x, ve0);
        float y2 = fmaf(Ml10, pv.x, fmaf(Ml11, pv.y, ve1));

        const float inv_n1 = 1.0f / (float)(n - 1);
        const float k1 = 1.0f / de;
        const float k2 = 1.0f / at + k1;
        const float t0 = (float)tbase * inv_n1;
        float e1 = g * __expf(-t0 * k1);
        float e2 = g * __expf(-t0 * k2);
        const float r1c = __expf(-inv_n1 * k1);
        const float r2c = __expf(-inv_n1 * k2);

        if (tbase + ITEMS <= n) {
            const float4* xp = (const float4*)(x + tbase);   // L1/L2-resident reload
            float4* op = (float4*)(out + tbase);
            #pragma unroll
            for (int k = 0; k < ITEMS / 4; k++) {
                float4 q = xp[k];
                float4 o;
                #pragma unroll
                for (int s = 0; s < 4; s++) {
                    float xn = (s == 0) ? q.x : (s == 1) ? q.y : (s == 2) ? q.z : q.w;
                    float t  = fmaf(dcoef, y1, bb * xn);   // off-chain
                    y2 = fmaf(c2, y2, t);                  // 4-cyc chain
                    y1 = fmaf(c1, y1, b1 * xn);            // 4-cyc chain
                    float val = y2 * (e1 - e2);
                    e1 *= r1c; e2 *= r2c;
                    if (s == 0) o.x = val; else if (s == 1) o.y = val;
                    else if (s == 2) o.z = val; else o.w = val;
                }
                op[k] = o;
            }
        } else if (tbase < n) {
            #pragma unroll
            for (int j = 0; j < ITEMS; j++) {
                long idx = tbase + j;
                float xn = (idx < n) ? x[idx] : 0.0f;
                float t  = fmaf(dcoef, y1, bb * xn);
                y2 = fmaf(c2, y2, t);
                y1 = fmaf(c1, y1, b1 * xn);
                float val = y2 * (e1 - e2);
                e1 *= r1c; e2 *= r2c;
                if (idx < n) out[idx] = val;
            }
        }
    }
}

// ---------------------------------------------------------------------------
extern "C" void kernel_launch(void* const* d_in, const int* in_sizes, int n_in,
                              void* d_out, int out_size) {
    int i_par = 0, i_noise = 1;
    if (n_in >= 2 && in_sizes[0] > in_sizes[1]) { i_par = 1; i_noise = 0; }
    const float* params = (const float*)d_in[i_par];
    const float* noise  = (const float*)d_in[i_noise];
    float* out = (float*)d_out;
    const int n = in_sizes[i_noise];
    const int G = (n + OUTS - 1) / OUTS;   // n = 2^22 -> G = 631 (one wave @5 CTA/SM)

    ng_one<<<G, BLOCK>>>(params, noise, out, n);
}

// round 11
// speedup vs baseline: 1.2751x; 1.2751x over previous
#include <cuda_runtime.h>

#define ITEMS 28
#define BLOCK 256
#define CHUNK (ITEMS * BLOCK)   // 7168 -> G=586; @5 CTA/SM capacity 740 => one wave
#define NWARP (BLOCK / 32)      // 8
#define MAXBLKS 1024
#define MAXTHR  (MAXBLKS * BLOCK)

__device__ float2 g_agg[MAXBLKS];   // per-block zero-state end state
__device__ float4 g_thrM[MAXTHR];   // per-thread exclusive matrix {m00,m10,m11,-}
__device__ float2 g_thrV[MAXTHR];   // per-thread exclusive zero-state vector

__device__ __forceinline__ void get_params(const float* __restrict__ p,
                                           float& c1, float& c2,
                                           float& attack, float& decay, float& gain) {
    attack = fmaxf(p[0], 1e-7f);
    decay  = fmaxf(p[1], 1e-7f);
    c1 = fminf(fmaxf(p[2], 1e-7f), 0.99f);   // lowpass
    c2 = fminf(fmaxf(p[3], 1e-7f), 0.99f);   // highpass
    gain = fmaxf(p[4], 1e-7f);
}

__device__ __forceinline__ void mat_mul(float& c00, float& c10, float& c11,
                                        float a00, float a10, float a11,
                                        float b00, float b10, float b11) {
    c00 = a00 * b00;
    c10 = fmaf(a10, b00, a11 * b10);
    c11 = a11 * b11;
}

__device__ __forceinline__ void mat_sq(float& m00, float& m10, float& m11) {
    float n00 = m00 * m00;
    float n10 = m10 * (m00 + m11);
    float n11 = m11 * m11;
    m00 = n00; m10 = n10; m11 = n11;
}

// P = A^28 (binary 11100): 5 squarings + 3 muls
__device__ __forceinline__ void mat_pow28(float a00, float a10, float a11,
                                          float& M00, float& M10, float& M11) {
    M00 = 1.0f; M10 = 0.0f; M11 = 1.0f;
    float p00 = a00, p10 = a10, p11 = a11;
    #pragma unroll
    for (int b = 0; b < 5; b++) {
        if ((28 >> b) & 1) {
            float t00, t10, t11;
            mat_mul(t00, t10, t11, M00, M10, M11, p00, p10, p11);
            M00 = t00; M10 = t10; M11 = t11;
        }
        mat_sq(p00, p10, p11);
    }
}

// ---------------------------------------------------------------------------
// Pass 1: streaming stride-4 sweep (prefetch, no xv array); vector-only KS
// scan; publish per-thread exclusive affine + block aggregate.
// ---------------------------------------------------------------------------
__global__ void __launch_bounds__(BLOCK, 5)
ng_pass1(const float* __restrict__ params, const float* __restrict__ x, int n) {
    float c1, c2, at, de, g;
    get_params(params, c1, c2, at, de, g);
    const float b1 = 1.0f - c1;
    const float dcoef = c2 * (c1 - 1.0f);
    const float bb = c2 * b1;

    const int tid = threadIdx.x;
    const int bid = blockIdx.x;
    const int lane = tid & 31, wid = tid >> 5;
    const long base = (long)bid * CHUNK + (long)tid * ITEMS;

    // stride-4 constants
    const float A2_00 = c1 * c1, A2_10 = dcoef * (c1 + c2), A2_11 = c2 * c2;
    const float A4_00 = A2_00 * A2_00, A4_10 = A2_10 * (A2_00 + A2_11), A4_11 = A2_11 * A2_11;
    const float q0x = b1,       q0y = bb;
    const float q1x = c1 * q0x, q1y = fmaf(dcoef, q0x, c2 * q0y);
    const float q2x = c1 * q1x, q2y = fmaf(dcoef, q1x, c2 * q1y);
    const float q3x = c1 * q2x, q3y = fmaf(dcoef, q2x, c2 * q2y);

    float v0 = 0.0f, v1 = 0.0f;
    if (base + ITEMS <= n) {
        const float4* xp = (const float4*)(x + base);
        float4 q = xp[0];
        #pragma unroll
        for (int k = 0; k < ITEMS / 4; k++) {
            float4 qn;
            if (k + 1 < ITEMS / 4) qn = xp[k + 1];
            float u0 = fmaf(q2x, q.y, q3x * q.x) + fmaf(q0x, q.w, q1x * q.z);
            float u1 = fmaf(q2y, q.y, q3y * q.x) + fmaf(q0y, q.w, q1y * q.z);
            float v0n = fmaf(A4_00, v0, u0);
            v1 = fmaf(A4_10, v0, fmaf(A4_11, v1, u1));
            v0 = v0n;
            q = qn;
        }
    } else if (base < n) {
        #pragma unroll
        for (int j = 0; j < ITEMS; j++) {
            long idx = base + j;
            float xn = (idx < n) ? x[idx] : 0.0f;
            float t  = fmaf(dcoef, v0, bb * xn);
            v1 = fmaf(c2, v1, t);
            v0 = fmaf(c1, v0, b1 * xn);
        }
    }

    // P = A^28
    float pk00, pk10, pk11;
    mat_pow28(c1, dcoef, c2, pk00, pk10, pk11);

    // vector-only KS scan with constant round matrices; Ml = P^lane
    float Ml00 = 1.0f, Ml10 = 0.0f, Ml11 = 1.0f;
    #pragma unroll
    for (int k = 0; k < 5; k++) {
        int dd = 1 << k;
        float o0 = __shfl_up_sync(0xffffffffu, v0, dd);
        float o1 = __shfl_up_sync(0xffffffffu, v1, dd);
        if (lane >= dd) {
            v0 = fmaf(pk00, o0, v0);
            v1 = fmaf(pk10, o0, fmaf(pk11, o1, v1));
        }
        if ((lane >> k) & 1) {
            float t00, t10, t11;
            mat_mul(t00, t10, t11, Ml00, Ml10, Ml11, pk00, pk10, pk11);
            Ml00 = t00; Ml10 = t10; Ml11 = t11;
        }
        mat_sq(pk00, pk10, pk11);   // ends: pk = P^32
    }

    float ve0 = __shfl_up_sync(0xffffffffu, v0, 1);
    float ve1 = __shfl_up_sync(0xffffffffu, v1, 1);
    if (lane == 0) { ve0 = 0.0f; ve1 = 0.0f; }

    __shared__ float2 wtotv[NWARP];
    __shared__ float2 prevv[NWARP];
    if (lane == 31) wtotv[wid] = make_float2(v0, v1);
    __syncthreads();
    if (tid == 0) {
        float s0 = 0.0f, s1 = 0.0f;
        #pragma unroll
        for (int w = 0; w < NWARP; w++) {
            prevv[w] = make_float2(s0, s1);
            float2 wv = wtotv[w];
            float ns0 = fmaf(pk00, s0, wv.x);
            s1 = fmaf(pk10, s0, fmaf(pk11, s1, wv.y));
            s0 = ns0;
        }
        g_agg[bid] = make_float2(s0, s1);
    }
    __syncthreads();

    // Mwid = (P^32)^wid
    float Mw00 = 1.0f, Mw10 = 0.0f, Mw11 = 1.0f;
    float w00 = pk00, w10 = pk10, w11 = pk11;
    #pragma unroll
    for (int k = 0; k < 3; k++) {
        if ((wid >> k) & 1) {
            float t00, t10, t11;
            mat_mul(t00, t10, t11, Mw00, Mw10, Mw11, w00, w10, w11);
            Mw00 = t00; Mw10 = t10; Mw11 = t11;
        }
        mat_sq(w00, w10, w11);
    }

    float Em00, Em10, Em11;
    mat_mul(Em00, Em10, Em11, Ml00, Ml10, Ml11, Mw00, Mw10, Mw11);
    float2 pv = prevv[wid];
    float Ev0 = fmaf(Ml00, pv.x, ve0);
    float Ev1 = fmaf(Ml10, pv.x, fmaf(Ml11, pv.y, ve1));

    const int gid = bid * BLOCK + tid;
    g_thrM[gid] = make_float4(Em00, Em10, Em11, 0.0f);
    g_thrV[gid] = make_float2(Ev0, Ev1);
}

// ---------------------------------------------------------------------------
// Pass 3: E-load + lookback + streamed replay (inline prefetched loads,
// streaming stores). No xv register array.
// ---------------------------------------------------------------------------
__global__ void __launch_bounds__(BLOCK, 5)
ng_pass3(const float* __restrict__ params, const float* __restrict__ x,
         float* __restrict__ out, int n) {
    float c1, c2, at, de, g;
    get_params(params, c1, c2, at, de, g);
    const float b1 = 1.0f - c1;
    const float dcoef = c2 * (c1 - 1.0f);
    const float bb = c2 * b1;

    const int tid  = threadIdx.x;
    const int bid  = blockIdx.x;
    const int lane = tid & 31, wid = tid >> 5;
    const long base = (long)bid * CHUNK + (long)tid * ITEMS;
    const bool full = (base + ITEMS) <= n;

    const int gid = bid * BLOCK + tid;
    float4 EM = __ldg(&g_thrM[gid]);
    float2 EV = __ldg(&g_thrV[gid]);

    // ---- powering: A_C = (A^28)^256; Ml = A_C^tid; S = A_C^256 ----
    float p00, p10, p11;
    mat_pow28(c1, dcoef, c2, p00, p10, p11);
    #pragma unroll
    for (int k = 0; k < 8; k++) mat_sq(p00, p10, p11);   // A_C = A^7168
    float Ml00 = 1.0f, Ml10 = 0.0f, Ml11 = 1.0f;
    #pragma unroll
    for (int b = 0; b < 8; b++) {
        if ((tid >> b) & 1) {
            float t00, t10, t11;
            mat_mul(t00, t10, t11, Ml00, Ml10, Ml11, p00, p10, p11);
            Ml00 = t00; Ml10 = t10; Ml11 = t11;
        }
        mat_sq(p00, p10, p11);
    }

    // ---- lookback ----
    float r0 = 0.0f, r1 = 0.0f;
    for (int dd = tid; dd < bid; dd += BLOCK) {
        float2 v = __ldg(&g_agg[bid - 1 - dd]);
        r0 = fmaf(Ml00, v.x, r0);
        r1 = fmaf(Ml10, v.x, fmaf(Ml11, v.y, r1));
        float t00, t10, t11;
        mat_mul(t00, t10, t11, Ml00, Ml10, Ml11, p00, p10, p11);
        Ml00 = t00; Ml10 = t10; Ml11 = t11;
    }
    #pragma unroll
    for (int dd = 16; dd > 0; dd >>= 1) {
        r0 += __shfl_xor_sync(0xffffffffu, r0, dd);
        r1 += __shfl_xor_sync(0xffffffffu, r1, dd);
    }
    __shared__ float2 wred[NWARP];
    if (lane == 0) wred[wid] = make_float2(r0, r1);
    __syncthreads();
    float sinx = 0.0f, siny = 0.0f;
    #pragma unroll
    for (int w = 0; w < NWARP; w++) { sinx += wred[w].x; siny += wred[w].y; }

    // ---- seed ----
    float y1 = fmaf(EM.x, sinx, EV.x);
    float y2 = fmaf(EM.y, sinx, fmaf(EM.z, siny, EV.y));

    // ---- envelope ----
    const float inv_n1 = 1.0f / (float)(n - 1);
    const float k1 = 1.0f / de;
    const float k2 = 1.0f / at + k1;
    const float t0 = (float)base * inv_n1;
    float e1 = g * __expf(-t0 * k1);
    float e2 = g * __expf(-t0 * k2);
    const float r1c = __expf(-inv_n1 * k1);
    const float r2c = __expf(-inv_n1 * k2);

    // ---- streamed replay: inline loads (L2-hot), prefetch one ahead,
    //      streaming stores ----
    if (full) {
        const float4* xp = (const float4*)(x + base);
        float4* op = (float4*)(out + base);
        float4 q = __ldg(&xp[0]);
        #pragma unroll
        for (int k = 0; k < ITEMS / 4; k++) {
            float4 qn;
            if (k + 1 < ITEMS / 4) qn = __ldg(&xp[k + 1]);
            float4 o;
            #pragma unroll
            for (int s = 0; s < 4; s++) {
                float xn = (s == 0) ? q.x : (s == 1) ? q.y : (s == 2) ? q.z : q.w;
                float t  = fmaf(dcoef, y1, bb * xn);   // off-chain
                y2 = fmaf(c2, y2, t);                  // 4-cyc chain
                y1 = fmaf(c1, y1, b1 * xn);            // 4-cyc chain
                float val = y2 * (e1 - e2);
                e1 *= r1c; e2 *= r2c;
                if (s == 0) o.x = val; else if (s == 1) o.y = val;
                else if (s == 2) o.z = val; else o.w = val;
            }
            __stcs(&op[k], o);
            q = qn;
        }
    } else if (base < n) {
        #pragma unroll
        for (int j = 0; j < ITEMS; j++) {
            long idx = base + j;
            float xn = (idx < n) ? x[idx] : 0.0f;
            float t  = fmaf(dcoef, y1, bb * xn);
            y2 = fmaf(c2, y2, t);
            y1 = fmaf(c1, y1, b1 * xn);
            float val = y2 * (e1 - e2);
            e1 *= r1c; e2 *= r2c;
            if (idx < n) out[idx] = val;
        }
    }
}

// ---------------------------------------------------------------------------
extern "C" void kernel_launch(void* const* d_in, const int* in_sizes, int n_in,
                              void* d_out, int out_size) {
    int i_par = 0, i_noise = 1;
    if (n_in >= 2 && in_sizes[0] > in_sizes[1]) { i_par = 1; i_noise = 0; }
    const float* params = (const float*)d_in[i_par];
    const float* noise  = (const float*)d_in[i_noise];
    float* out = (float*)d_out;
    const int n = in_sizes[i_noise];
    int G = (n + CHUNK - 1) / CHUNK;
    if (G > MAXBLKS) G = MAXBLKS;  // n = 2^22 -> G = 586

    ng_pass1<<<G, BLOCK>>>(params, noise, n);
    ng_pass3<<<G, BLOCK>>>(params, noise, out, n);
}